// round 14
// baseline (speedup 1.0000x reference)
#include <cuda_runtime.h>
#include <math_constants.h>

// GraphPoolMol: masked neighborhood max-pool over graph Laplacian sparsity.
// B=64, MAX_ATOM=128, N_FEAT=128.
// out[b,i,f] = max_{j: L[b,i,j]!=0, j<n, i<n} x[b,j,f]; 0 if i>=n.
// diag(L)=1 => for i<n the mask contains j=i (cnt>=1), so the reference's
// "no neighbor" fallback never fires for valid rows, and loading the self
// row as padding never changes the max.
//
// Warp-per-row. 256-thread blocks (8 rows of one batch), grid=1024.
// Gather: lane-parallel nth-bit extraction with self-row padding at lanes
// >= cnt, then a STATICALLY UNROLLED shfl+LDG+fmax loop (first 16 loads
// unconditional, rest warp-uniformly guarded) so ptxas batches loads across
// rounds (cross-round MLP) instead of serializing 250-cycle L2 epochs.

#define AT 128
#define NF 128
#define THREADS 256

__device__ __forceinline__ float4 fmax4(float4 a, float4 b) {
    return make_float4(fmaxf(a.x, b.x), fmaxf(a.y, b.y),
                       fmaxf(a.z, b.z), fmaxf(a.w, b.w));
}

// Position of the r-th (0-indexed) set bit of m; in-range garbage when
// r >= popc(m) (those lanes are overridden with the self row).
__device__ __forceinline__ int nth_bit(unsigned m, int r) {
    int j = 0, c;
    c = __popc(m & 0xFFFFu); if (r >= c) { r -= c; m >>= 16; j = 16; }
    c = __popc(m & 0xFFu);   if (r >= c) { r -= c; m >>= 8;  j += 8; }
    c = __popc(m & 0xFu);    if (r >= c) { r -= c; m >>= 4;  j += 4; }
    c = __popc(m & 0x3u);    if (r >= c) { r -= c; m >>= 2;  j += 2; }
    c = (int)(m & 1u);       if (r >= c) {                   j += 1; }
    return j;
}

__global__ __launch_bounds__(THREADS, 6)
void graph_pool_mol_kernel(const float* __restrict__ xg,
                           const float* __restrict__ Lg,
                           const int* __restrict__ mol_slice,
                           float* __restrict__ outg)
{
    const int b    = blockIdx.x >> 4;              // batch (16 blocks each)
    const int i    = ((blockIdx.x & 15) << 3) + (threadIdx.x >> 5); // row
    const int lane = threadIdx.x & 31;

    // Issue both long-latency loads before anything depends on either.
    const int n = __ldg(mol_slice + 2 * b);        // mol_slice[b,0] = n_atoms
    const float4 Lv = __ldg(reinterpret_cast<const float4*>(
                                Lg + ((size_t)b * AT + i) * AT) + lane);

    float4* outr = reinterpret_cast<float4*>(outg) + ((size_t)b * AT + i) * 32;

    if (i >= n) {                                  // padded row
        outr[lane] = make_float4(0.f, 0.f, 0.f, 0.f);
        return;
    }

    // ---- Warp-uniform 128-bit mask (ballot word q: col = 4*bit + q) -------
    const int j0 = 4 * lane;
    const unsigned m0 = __ballot_sync(0xffffffffu, (Lv.x != 0.f) && (j0 + 0 < n));
    const unsigned m1 = __ballot_sync(0xffffffffu, (Lv.y != 0.f) && (j0 + 1 < n));
    const unsigned m2 = __ballot_sync(0xffffffffu, (Lv.z != 0.f) && (j0 + 2 < n));
    const unsigned m3 = __ballot_sync(0xffffffffu, (Lv.w != 0.f) && (j0 + 3 < n));

    const int c0 = __popc(m0), c1 = __popc(m1), c2 = __popc(m2);
    const int cnt = c0 + c1 + c2 + __popc(m3);     // >= 1 (diagonal)

    const float4* xb = reinterpret_cast<const float4*>(xg + (size_t)b * AT * NF);
    float4 acc0 = make_float4(-CUDART_INF_F, -CUDART_INF_F,
                              -CUDART_INF_F, -CUDART_INF_F);
    float4 acc1 = acc0;

    int done = 0;
    while (done < cnt) {                           // one pass unless cnt > 32
        // Lane s extracts the (done+s)-th set column; lanes past cnt get the
        // self row i (harmless padding for max).
        const int t = done + lane;
        unsigned m = m0; int q = 0;
        int tt = t;
        if (tt >= c0) { tt -= c0; m = m1; q = 1;
            if (tt >= c1) { tt -= c1; m = m2; q = 2;
                if (tt >= c2) { tt -= c2; m = m3; q = 3; } } }
        int jmine = 4 * nth_bit(m, min(tt, 31)) + q;   // in [0,127]
        jmine = (t < cnt) ? jmine : i;                 // self-row padding

        const int cm = min(cnt - done, 32);

        // Rounds 1-4: 16 unconditional loads (padding = self row, L1-hot).
        #pragma unroll
        for (int r = 0; r < 4; ++r) {
            const int ja = __shfl_sync(0xffffffffu, jmine, 4 * r + 0);
            const int jb = __shfl_sync(0xffffffffu, jmine, 4 * r + 1);
            const int jc = __shfl_sync(0xffffffffu, jmine, 4 * r + 2);
            const int jd = __shfl_sync(0xffffffffu, jmine, 4 * r + 3);
            const float4 va = __ldg(xb + ja * 32 + lane);
            const float4 vb = __ldg(xb + jb * 32 + lane);
            const float4 vc = __ldg(xb + jc * 32 + lane);
            const float4 vd = __ldg(xb + jd * 32 + lane);
            acc0 = fmax4(acc0, va);
            acc1 = fmax4(acc1, vb);
            acc0 = fmax4(acc0, vc);
            acc1 = fmax4(acc1, vd);
        }
        // Rounds 5-8: warp-uniformly guarded (only for dense rows).
        #pragma unroll
        for (int r = 4; r < 8; ++r) {
            if (4 * r < cm) {
                const int ja = __shfl_sync(0xffffffffu, jmine, 4 * r + 0);
                const int jb = __shfl_sync(0xffffffffu, jmine, 4 * r + 1);
                const int jc = __shfl_sync(0xffffffffu, jmine, 4 * r + 2);
                const int jd = __shfl_sync(0xffffffffu, jmine, 4 * r + 3);
                const float4 va = __ldg(xb + ja * 32 + lane);
                const float4 vb = __ldg(xb + jb * 32 + lane);
                const float4 vc = __ldg(xb + jc * 32 + lane);
                const float4 vd = __ldg(xb + jd * 32 + lane);
                acc0 = fmax4(acc0, va);
                acc1 = fmax4(acc1, vb);
                acc0 = fmax4(acc0, vc);
                acc1 = fmax4(acc1, vd);
            }
        }
        done += cm;
    }

    outr[lane] = fmax4(acc0, acc1);
}

extern "C" void kernel_launch(void* const* d_in, const int* in_sizes, int n_in,
                              void* d_out, int out_size)
{
    const float* node_features = (const float*)d_in[0];
    const float* laplacian     = (const float*)d_in[1];
    const int*   mol_slice     = (const int*)d_in[2];
    // d_in[3] = l_slice (unused)

    float* out = (float*)d_out;

    const int B = 64;
    const int blocks = B * (AT / 8);               // 1024 blocks, 8 rows each
    graph_pool_mol_kernel<<<blocks, THREADS>>>(
        node_features, laplacian, mol_slice, out);
}